// round 10
// baseline (speedup 1.0000x reference)
#include <cuda_runtime.h>
#include <cuda_bf16.h>
#include <cstdint>
#include <math_constants.h>

#define BATCH 16
#define HEADS 8
#define SEQ   1024
#define DIM   64

// ---------------- scratch ----------------
__device__ int g_i0[BATCH*SEQ];
__device__ int g_i1[BATCH*SEQ];
__device__ int g_list[BATCH*2*SEQ];
__device__ int g_cnt[BATCH*2];

// Flat bf16 hi/lo arrays, same [b,h,s,d] layout as inputs. 16 MB each.
#define NELEM (BATCH*HEADS*SEQ*DIM)
__device__ __align__(16) unsigned char gQh[NELEM*2];
__device__ __align__(16) unsigned char gQl[NELEM*2];
__device__ __align__(16) unsigned char gKh[NELEM*2];
__device__ __align__(16) unsigned char gKl[NELEM*2];
__device__ __align__(16) unsigned char gVh[NELEM*2];
__device__ __align__(16) unsigned char gVl[NELEM*2];

// ---------------- asm helpers (sm_80-level PTX only) ----------------
__device__ __forceinline__ uint32_t smem_u32(const void* p) {
    uint32_t a;
    asm("{ .reg .u64 t; cvta.to.shared.u64 t, %1; cvt.u32.u64 %0, t; }" : "=r"(a) : "l"(p));
    return a;
}
__device__ __forceinline__ void ldsm_x4(uint32_t* r, uint32_t addr) {
    asm volatile("ldmatrix.sync.aligned.m8n8.x4.shared.b16 {%0,%1,%2,%3}, [%4];"
        : "=r"(r[0]), "=r"(r[1]), "=r"(r[2]), "=r"(r[3]) : "r"(addr));
}
__device__ __forceinline__ void ldsm_x4t(uint32_t* r, uint32_t addr) {
    asm volatile("ldmatrix.sync.aligned.m8n8.x4.trans.shared.b16 {%0,%1,%2,%3}, [%4];"
        : "=r"(r[0]), "=r"(r[1]), "=r"(r[2]), "=r"(r[3]) : "r"(addr));
}
__device__ __forceinline__ void mma16816(float* d, const uint32_t* a, const uint32_t* b) {
    asm volatile("mma.sync.aligned.m16n8k16.row.col.f32.bf16.bf16.f32 "
        "{%0,%1,%2,%3}, {%4,%5,%6,%7}, {%8,%9}, {%0,%1,%2,%3};"
        : "+f"(d[0]), "+f"(d[1]), "+f"(d[2]), "+f"(d[3])
        : "r"(a[0]), "r"(a[1]), "r"(a[2]), "r"(a[3]), "r"(b[0]), "r"(b[1]));
}
#define CP16(dst, src) asm volatile("cp.async.cg.shared.global [%0], [%1], 16;" :: "r"(dst), "l"(src))
#define CP_COMMIT()    asm volatile("cp.async.commit_group;" ::: "memory")
#define CP_WAIT(n)     asm volatile("cp.async.wait_group %0;" :: "n"(n) : "memory")

__device__ __forceinline__ void split2(float a, float b, uint32_t& h, uint32_t& l) {
    __nv_bfloat162 hv = __floats2bfloat162_rn(a, b);
    float2 hf = __bfloat1622float2(hv);
    __nv_bfloat162 lv = __floats2bfloat162_rn(a - hf.x, b - hf.y);
    h = *reinterpret_cast<uint32_t*>(&hv);
    l = *reinterpret_cast<uint32_t*>(&lv);
}

// ---------------- init + pairs (exact, unchanged) ----------------
__global__ void init_kernel() {
    int t = threadIdx.x;
    if (t < BATCH*2) g_cnt[t] = 0;
}

__global__ __launch_bounds__(256) void pairs_kernel(const float* __restrict__ centers) {
    int bs = blockIdx.x;
    int b = bs >> 10, s = bs & 1023;
    const float4* cp = (const float4*)centers;
    float4 bb = cp[bs];
    float x1 = bb.x - 0.5f*bb.w, y1 = bb.y - 0.5f*bb.z;
    float x2 = bb.x + 0.5f*bb.w, y2 = bb.y + 0.5f*bb.z;
    float areas = __fmul_rn(__fsub_rn(x2,x1), __fsub_rn(y2,y1));
    float best = -CUDART_INF_F; int bidx = 0;
    for (int k = threadIdx.x; k < SEQ; k += 256) {
        float4 cb = cp[(b<<10)+k];
        float kx1 = cb.x - 0.5f*cb.w, ky1 = cb.y - 0.5f*cb.z;
        float kx2 = cb.x + 0.5f*cb.w, ky2 = cb.y + 0.5f*cb.z;
        float iw = __fsub_rn(fminf(x2,kx2), fmaxf(x1,kx1));
        float ih = __fsub_rn(fminf(y2,ky2), fmaxf(y1,ky1));
        float inter = __fmul_rn(iw, ih);
        float ka = __fmul_rn(__fsub_rn(kx2,kx1), __fsub_rn(ky2,ky1));
        float uni = __fsub_rn(__fadd_rn(areas, ka), inter);
        float iou = __fdiv_rn(inter, uni);
        if (k == s) iou = __fsub_rn(iou, 1.0f);
        if (iou > best) { best = iou; bidx = k; }
    }
    __shared__ float sv[256]; __shared__ int si[256];
    int t = threadIdx.x;
    sv[t] = best; si[t] = bidx;
    __syncthreads();
    for (int off = 128; off > 0; off >>= 1) {
        if (t < off) {
            float v2 = sv[t+off]; int i2 = si[t+off];
            if (v2 > sv[t] || (v2 == sv[t] && i2 < si[t])) { sv[t] = v2; si[t] = i2; }
        }
        __syncthreads();
    }
    if (t == 0) {
        int p = si[0];
        float l1s = __fadd_rn(fabsf(__fsub_rn(x2,x1)), fabsf(__fsub_rn(y2,y1)));
        float4 pb = cp[(b<<10)+p];
        float px1 = pb.x - 0.5f*pb.w, py1 = pb.y - 0.5f*pb.z;
        float px2 = pb.x + 0.5f*pb.w, py2 = pb.y + 0.5f*pb.z;
        float l1p = __fadd_rn(fabsf(__fsub_rn(px2,px1)), fabsf(__fsub_rn(py2,py1)));
        bool keep0 = (l1s >= l1p);
        g_i0[bs] = keep0 ? s : p;
        g_i1[bs] = keep0 ? p : s;
        int g = keep0 ? 0 : 1;
        int slot = atomicAdd(&g_cnt[b*2 + g], 1);
        g_list[(b*2 + g)*SEQ + slot] = s;
    }
}

// ---------------- streaming fp32 -> bf16 hi/lo convert ----------------
__global__ __launch_bounds__(256) void convert_kernel(
    const float* __restrict__ Q, const float* __restrict__ K, const float* __restrict__ V)
{
    int tid = blockIdx.x*256 + threadIdx.x;              // float4 index
    int which = blockIdx.y;
    const float4* s = (const float4*)(which == 0 ? Q : (which == 1 ? K : V));
    uint2* dh = (uint2*)(which == 0 ? gQh : (which == 1 ? gKh : gVh));
    uint2* dl = (uint2*)(which == 0 ? gQl : (which == 1 ? gKl : gVl));
    float4 v = s[tid];
    uint2 uh, ul;
    split2(v.x, v.y, uh.x, ul.x);
    split2(v.z, v.w, uh.y, ul.y);
    dh[tid] = uh;
    dl[tid] = ul;
}

// ---------------- HMMA flash attention: 64 q-rows, 32-key tiles, 128 thr ----------------
// smem: Qh 64x272=17408, Ql 17408, 2 KV bufs {Kh,Kl,Vh,Vl} 32x272=8704 each
// -> 34816/buf; idx 8192. Total 112640 (= 2 CTAs/SM).
#define QSTR   272
#define OQH    0
#define OQL    17408
#define OKV    34816
#define KVBUF  34816
#define OFF_KH 0
#define OFF_KL 8704
#define OFF_VH 17408
#define OFF_VL 26112
#define OIDX0  104448
#define OIDX1  (104448 + 4096)
#define ASMEM  (104448 + 8192)

__global__ __launch_bounds__(128, 2) void attn_kernel(float* __restrict__ out) {
    int tile = blockIdx.x, h = blockIdx.y, b = blockIdx.z;
    int g = h >> 2;
    int cnt = g_cnt[b*2 + g];
    if (tile*64 >= cnt) return;

    extern __shared__ char sm[];
    uint32_t sb = smem_u32(sm);
    int t = threadIdx.x, lane = t & 31, w = t >> 5;
    int* si0 = (int*)(sm + OIDX0);
    int* si1 = (int*)(sm + OIDX1);

    // stage pair indices for this batch into smem
    {
        const int* p0 = g_i0 + b*SEQ;
        const int* p1 = g_i1 + b*SEQ;
        #pragma unroll
        for (int i = 0; i < 8; i++) {
            si0[t + i*128] = p0[t + i*128];
            si1[t + i*128] = p1[t + i*128];
        }
    }
    __syncthreads();

    const size_t rowbase = (size_t)(b*HEADS + h) * SEQ;   // 128 B source rows
    const int* listp = g_list + (b*2+g)*SEQ;

    // ---- Q tile gather: thread = one (row, half); 8+8 cp16 ----
    {
        int row = t >> 1, half = t & 1;
        int idx = tile*64 + row; if (idx >= cnt) idx = cnt - 1;
        int q = listp[idx];
        int src = half ? si1[q] : si0[q];
        size_t go = (rowbase + src) * 128;
        uint32_t dq = sb + (half ? 128u : 0u) + (uint32_t)row*QSTR;
        #pragma unroll
        for (int j = 0; j < 8; j++) {
            CP16(dq + OQH + j*16, gQh + go + j*16);
            CP16(dq + OQL + j*16, gQl + go + j*16);
        }
    }

    // ---- K/V tile gather issuer: 32 keys x 2 halves x 2 cols = 128 slots ----
    auto issue = [&](int kt, int buf) {
        int key = t >> 2, half = (t >> 1) & 1, c = t & 1;
        int k = kt*32 + key;
        int src = half ? si1[k] : si0[k];
        size_t go = (rowbase + src) * 128 + c*64;
        uint32_t base = sb + OKV + buf*KVBUF + (uint32_t)key*QSTR + half*128 + c*64;
        #pragma unroll
        for (int j = 0; j < 4; j++) {
            CP16(base + OFF_KH + j*16, gKh + go + j*16);
            CP16(base + OFF_KL + j*16, gKl + go + j*16);
            CP16(base + OFF_VH + j*16, gVh + go + j*16);
            CP16(base + OFF_VL + j*16, gVl + go + j*16);
        }
    };

    issue(0, 0);
    CP_COMMIT();

    // per-lane ldmatrix offsets
    int l15 = lane & 15;
    uint32_t aH = sb + OQH + (w*16 + l15)*QSTR + (lane >> 4)*16;
    uint32_t aL = sb + OQL + (w*16 + l15)*QSTR + (lane >> 4)*16;
    uint32_t bOff4 = (lane & 7)*QSTR + ((lane >> 3) & 3)*16;   // K x4
    uint32_t vOff4 = (uint32_t)l15*QSTR + (lane >> 4)*16;      // V x4t

    float st[16], ot[64];
    #pragma unroll
    for (int i = 0; i < 64; i++) ot[i] = 0.f;
    float mref0 = 0.f, mref1 = 0.f, lr0 = 0.f, lr1 = 0.f;
    int buf = 0;

    for (int kt = 0; kt < 32; kt++) {
        if (kt < 31) { issue(kt+1, buf ^ 1); CP_COMMIT(); CP_WAIT(1); }
        else         { CP_WAIT(0); }
        __syncthreads();

        uint32_t kbH = sb + OKV + buf*KVBUF + OFF_KH + bOff4;
        uint32_t kbL = sb + OKV + buf*KVBUF + OFF_KL + bOff4;
        uint32_t vbH = sb + OKV + buf*KVBUF + OFF_VH + vOff4;
        uint32_t vbL = sb + OKV + buf*KVBUF + OFF_VL + vOff4;

        // ---- QK: S = QhKh + QhKl + QlKh  (k-step pairs, 4 key-blocks) ----
        #pragma unroll
        for (int i = 0; i < 16; i++) st[i] = 0.f;
        #pragma unroll
        for (int ksp = 0; ksp < 4; ksp++) {
            uint32_t ah0[4], al0[4], ah1[4], al1[4];
            ldsm_x4(ah0, aH + (2*ksp)*32);
            ldsm_x4(al0, aL + (2*ksp)*32);
            ldsm_x4(ah1, aH + (2*ksp+1)*32);
            ldsm_x4(al1, aL + (2*ksp+1)*32);
            #pragma unroll
            for (int nt = 0; nt < 4; nt++) {
                uint32_t bh[4], bl[4];
                ldsm_x4(bh, kbH + nt*8*QSTR + ksp*64);
                ldsm_x4(bl, kbL + nt*8*QSTR + ksp*64);
                mma16816(st + nt*4, ah0, bh);
                mma16816(st + nt*4, ah0, bl);
                mma16816(st + nt*4, al0, bh);
                mma16816(st + nt*4, ah1, bh + 2);
                mma16816(st + nt*4, ah1, bl + 2);
                mma16816(st + nt*4, al1, bh + 2);
            }
        }

        // ---- softmax (fixed reference from tile 0) ----
        if (kt == 0) {
            float m0 = -CUDART_INF_F, m1 = -CUDART_INF_F;
            #pragma unroll
            for (int nt = 0; nt < 4; nt++) {
                m0 = fmaxf(m0, fmaxf(st[nt*4],   st[nt*4+1]));
                m1 = fmaxf(m1, fmaxf(st[nt*4+2], st[nt*4+3]));
            }
            m0 = fmaxf(m0, __shfl_xor_sync(0xffffffffu, m0, 1));
            m0 = fmaxf(m0, __shfl_xor_sync(0xffffffffu, m0, 2));
            m1 = fmaxf(m1, __shfl_xor_sync(0xffffffffu, m1, 1));
            m1 = fmaxf(m1, __shfl_xor_sync(0xffffffffu, m1, 2));
            mref0 = m0; mref1 = m1;
        }
        uint32_t pph0[4], pph1[4], ppl0[4], ppl1[4];
        #pragma unroll
        for (int nt = 0; nt < 4; nt++) {
            float p00 = __expf(st[nt*4]   - mref0);
            float p01 = __expf(st[nt*4+1] - mref0);
            float p10 = __expf(st[nt*4+2] - mref1);
            float p11 = __expf(st[nt*4+3] - mref1);
            lr0 += p00 + p01;
            lr1 += p10 + p11;
            split2(p00, p01, pph0[nt], ppl0[nt]);
            split2(p10, p11, pph1[nt], ppl1[nt]);
        }

        // ---- PV: O += PhVh + PhVl + PlVh  (2 key sub-tiles of 16) ----
        #pragma unroll
        for (int tt = 0; tt < 2; tt++) {
            uint32_t aPh[4] = { pph0[2*tt], pph1[2*tt], pph0[2*tt+1], pph1[2*tt+1] };
            uint32_t aPl[4] = { ppl0[2*tt], ppl1[2*tt], ppl0[2*tt+1], ppl1[2*tt+1] };
            #pragma unroll
            for (int ntp = 0; ntp < 8; ntp++) {
                uint32_t vh[4], vl[4];
                ldsm_x4t(vh, vbH + tt*16*QSTR + ntp*32);
                ldsm_x4t(vl, vbL + tt*16*QSTR + ntp*32);
                mma16816(ot + (2*ntp)*4,   aPh, vh);
                mma16816(ot + (2*ntp)*4,   aPh, vl);
                mma16816(ot + (2*ntp)*4,   aPl, vh);
                mma16816(ot + (2*ntp+1)*4, aPh, vh + 2);
                mma16816(ot + (2*ntp+1)*4, aPh, vl + 2);
                mma16816(ot + (2*ntp+1)*4, aPl, vh + 2);
            }
        }
        __syncthreads();
        buf ^= 1;
    }

    // ---- epilogue ----
    lr0 += __shfl_xor_sync(0xffffffffu, lr0, 1);
    lr0 += __shfl_xor_sync(0xffffffffu, lr0, 2);
    lr1 += __shfl_xor_sync(0xffffffffu, lr1, 1);
    lr1 += __shfl_xor_sync(0xffffffffu, lr1, 2);
    float inv0 = 0.08838834764831845f / lr0;   // 1/sqrt(2D)
    float inv1 = 0.08838834764831845f / lr1;

    int r0 = tile*64 + w*16 + (lane >> 2);
    int colb = (lane & 3) * 2;
    if (r0 < cnt) {
        int q = listp[r0];
        float* op = out + ((size_t)(b*SEQ + q))*512 + (h & 3)*128;
        #pragma unroll
        for (int nt = 0; nt < 16; nt++)
            *(float2*)(op + nt*8 + colb) = make_float2(ot[nt*4]*inv0, ot[nt*4+1]*inv0);
    }
    int r1 = r0 + 8;
    if (r1 < cnt) {
        int q = listp[r1];
        float* op = out + ((size_t)(b*SEQ + q))*512 + (h & 3)*128;
        #pragma unroll
        for (int nt = 0; nt < 16; nt++)
            *(float2*)(op + nt*8 + colb) = make_float2(ot[nt*4+2]*inv1, ot[nt*4+3]*inv1);
    }
}

// ---------------- launch ----------------
extern "C" void kernel_launch(void* const* d_in, const int* in_sizes, int n_in,
                              void* d_out, int out_size) {
    const float* Q = (const float*)d_in[0];
    const float* K = (const float*)d_in[1];
    const float* V = (const float*)d_in[2];
    const float* C = (const float*)d_in[3];
    float* out = (float*)d_out;

    cudaFuncSetAttribute(attn_kernel, cudaFuncAttributeMaxDynamicSharedMemorySize, ASMEM);

    init_kernel<<<1, 32>>>();
    pairs_kernel<<<BATCH*SEQ, 256>>>(C);
    convert_kernel<<<dim3(NELEM/1024, 3), 256>>>(Q, K, V);
    attn_kernel<<<dim3(16, HEADS, BATCH), 128, ASMEM>>>(out);
}

// round 14
// speedup vs baseline: 1.1139x; 1.1139x over previous
#include <cuda_runtime.h>
#include <cuda_bf16.h>
#include <cstdint>
#include <math_constants.h>

#define BATCH 16
#define HEADS 8
#define SEQ   1024
#define DIM   64

// ---------------- scratch ----------------
__device__ int g_i0[BATCH*SEQ];
__device__ int g_i1[BATCH*SEQ];
__device__ int g_list[BATCH*2*SEQ];
__device__ int g_cnt[BATCH*2];

// Flat bf16 hi/lo arrays, same [b,h,s,d] layout as inputs. 16 MB each.
#define NELEM (BATCH*HEADS*SEQ*DIM)
__device__ __align__(16) unsigned char gQh[NELEM*2];
__device__ __align__(16) unsigned char gQl[NELEM*2];
__device__ __align__(16) unsigned char gKh[NELEM*2];
__device__ __align__(16) unsigned char gKl[NELEM*2];
__device__ __align__(16) unsigned char gVh[NELEM*2];
__device__ __align__(16) unsigned char gVl[NELEM*2];

// ---------------- asm helpers (sm_80-level PTX only) ----------------
__device__ __forceinline__ uint32_t smem_u32(const void* p) {
    uint32_t a;
    asm("{ .reg .u64 t; cvta.to.shared.u64 t, %1; cvt.u32.u64 %0, t; }" : "=r"(a) : "l"(p));
    return a;
}
__device__ __forceinline__ void ldsm_x4(uint32_t* r, uint32_t addr) {
    asm volatile("ldmatrix.sync.aligned.m8n8.x4.shared.b16 {%0,%1,%2,%3}, [%4];"
        : "=r"(r[0]), "=r"(r[1]), "=r"(r[2]), "=r"(r[3]) : "r"(addr));
}
__device__ __forceinline__ void ldsm_x4t(uint32_t* r, uint32_t addr) {
    asm volatile("ldmatrix.sync.aligned.m8n8.x4.trans.shared.b16 {%0,%1,%2,%3}, [%4];"
        : "=r"(r[0]), "=r"(r[1]), "=r"(r[2]), "=r"(r[3]) : "r"(addr));
}
__device__ __forceinline__ void mma16816(float* d, const uint32_t* a, const uint32_t* b) {
    asm volatile("mma.sync.aligned.m16n8k16.row.col.f32.bf16.bf16.f32 "
        "{%0,%1,%2,%3}, {%4,%5,%6,%7}, {%8,%9}, {%0,%1,%2,%3};"
        : "+f"(d[0]), "+f"(d[1]), "+f"(d[2]), "+f"(d[3])
        : "r"(a[0]), "r"(a[1]), "r"(a[2]), "r"(a[3]), "r"(b[0]), "r"(b[1]));
}
#define CP16(dst, src) asm volatile("cp.async.cg.shared.global [%0], [%1], 16;" :: "r"(dst), "l"(src))
#define CP_COMMIT()    asm volatile("cp.async.commit_group;" ::: "memory")
#define CP_WAIT(n)     asm volatile("cp.async.wait_group %0;" :: "n"(n) : "memory")

__device__ __forceinline__ void split2(float a, float b, uint32_t& h, uint32_t& l) {
    __nv_bfloat162 hv = __floats2bfloat162_rn(a, b);
    float2 hf = __bfloat1622float2(hv);
    __nv_bfloat162 lv = __floats2bfloat162_rn(a - hf.x, b - hf.y);
    h = *reinterpret_cast<uint32_t*>(&hv);
    l = *reinterpret_cast<uint32_t*>(&lv);
}

// ---------------- init + pairs (exact, unchanged) ----------------
__global__ void init_kernel() {
    int t = threadIdx.x;
    if (t < BATCH*2) g_cnt[t] = 0;
}

__global__ __launch_bounds__(256) void pairs_kernel(const float* __restrict__ centers) {
    int bs = blockIdx.x;
    int b = bs >> 10, s = bs & 1023;
    const float4* cp = (const float4*)centers;
    float4 bb = cp[bs];
    float x1 = bb.x - 0.5f*bb.w, y1 = bb.y - 0.5f*bb.z;
    float x2 = bb.x + 0.5f*bb.w, y2 = bb.y + 0.5f*bb.z;
    float areas = __fmul_rn(__fsub_rn(x2,x1), __fsub_rn(y2,y1));
    float best = -CUDART_INF_F; int bidx = 0;
    for (int k = threadIdx.x; k < SEQ; k += 256) {
        float4 cb = cp[(b<<10)+k];
        float kx1 = cb.x - 0.5f*cb.w, ky1 = cb.y - 0.5f*cb.z;
        float kx2 = cb.x + 0.5f*cb.w, ky2 = cb.y + 0.5f*cb.z;
        float iw = __fsub_rn(fminf(x2,kx2), fmaxf(x1,kx1));
        float ih = __fsub_rn(fminf(y2,ky2), fmaxf(y1,ky1));
        float inter = __fmul_rn(iw, ih);
        float ka = __fmul_rn(__fsub_rn(kx2,kx1), __fsub_rn(ky2,ky1));
        float uni = __fsub_rn(__fadd_rn(areas, ka), inter);
        float iou = __fdiv_rn(inter, uni);
        if (k == s) iou = __fsub_rn(iou, 1.0f);
        if (iou > best) { best = iou; bidx = k; }
    }
    __shared__ float sv[256]; __shared__ int si[256];
    int t = threadIdx.x;
    sv[t] = best; si[t] = bidx;
    __syncthreads();
    for (int off = 128; off > 0; off >>= 1) {
        if (t < off) {
            float v2 = sv[t+off]; int i2 = si[t+off];
            if (v2 > sv[t] || (v2 == sv[t] && i2 < si[t])) { sv[t] = v2; si[t] = i2; }
        }
        __syncthreads();
    }
    if (t == 0) {
        int p = si[0];
        float l1s = __fadd_rn(fabsf(__fsub_rn(x2,x1)), fabsf(__fsub_rn(y2,y1)));
        float4 pb = cp[(b<<10)+p];
        float px1 = pb.x - 0.5f*pb.w, py1 = pb.y - 0.5f*pb.z;
        float px2 = pb.x + 0.5f*pb.w, py2 = pb.y + 0.5f*pb.z;
        float l1p = __fadd_rn(fabsf(__fsub_rn(px2,px1)), fabsf(__fsub_rn(py2,py1)));
        bool keep0 = (l1s >= l1p);
        g_i0[bs] = keep0 ? s : p;
        g_i1[bs] = keep0 ? p : s;
        int g = keep0 ? 0 : 1;
        int slot = atomicAdd(&g_cnt[b*2 + g], 1);
        g_list[(b*2 + g)*SEQ + slot] = s;
    }
}

// ---------------- streaming fp32 -> bf16 hi/lo convert ----------------
__global__ __launch_bounds__(256) void convert_kernel(
    const float* __restrict__ Q, const float* __restrict__ K, const float* __restrict__ V)
{
    int tid = blockIdx.x*256 + threadIdx.x;              // float4 index
    int which = blockIdx.y;
    const float4* s = (const float4*)(which == 0 ? Q : (which == 1 ? K : V));
    uint2* dh = (uint2*)(which == 0 ? gQh : (which == 1 ? gKh : gVh));
    uint2* dl = (uint2*)(which == 0 ? gQl : (which == 1 ? gKl : gVl));
    float4 v = s[tid];
    uint2 uh, ul;
    split2(v.x, v.y, uh.x, ul.x);
    split2(v.z, v.w, uh.y, ul.y);
    dh[tid] = uh;
    dl[tid] = ul;
}

// ---------------- HMMA flash attention: deferred-PV pipeline ----------------
// smem: Qh 128x272=34816, Ql 34816, 2 KV bufs {Kh,Kl,Vh,Vl} 64x272=17408 each
// -> 69632/buf; idx 8192. Total 217088 (1 CTA/SM).
#define QSTR   272
#define OQH    0
#define OQL    34816
#define OKV    69632
#define KVBUF  69632
#define OFF_KH 0
#define OFF_KL 17408
#define OFF_VH 34816
#define OFF_VL 52224
#define OIDX0  208896
#define OIDX1  (208896 + 4096)
#define ASMEM  (208896 + 8192)

__global__ __launch_bounds__(256, 1) void attn_kernel(float* __restrict__ out) {
    int tile = blockIdx.x, h = blockIdx.y, b = blockIdx.z;
    int g = h >> 2;
    int cnt = g_cnt[b*2 + g];
    if (tile*128 >= cnt) return;

    extern __shared__ char sm[];
    uint32_t sb = smem_u32(sm);
    int t = threadIdx.x, lane = t & 31, w = t >> 5;
    int* si0 = (int*)(sm + OIDX0);
    int* si1 = (int*)(sm + OIDX1);

    // stage pair indices for this batch into smem
    {
        const int* p0 = g_i0 + b*SEQ;
        const int* p1 = g_i1 + b*SEQ;
        #pragma unroll
        for (int i = 0; i < 4; i++) {
            si0[t + i*256] = p0[t + i*256];
            si1[t + i*256] = p1[t + i*256];
        }
    }
    __syncthreads();

    const size_t rowbase = (size_t)(b*HEADS + h) * SEQ;   // 128 B source rows
    const int* listp = g_list + (b*2+g)*SEQ;

    // ---- Q tile gather: thread = one (row, half); 8+8 cp16 ----
    {
        int row = t >> 1, half = t & 1;
        int idx = tile*128 + row; if (idx >= cnt) idx = cnt - 1;
        int q = listp[idx];
        int src = half ? si1[q] : si0[q];
        size_t go = (rowbase + src) * 128;
        uint32_t dq = sb + (half ? 128u : 0u) + (uint32_t)row*QSTR;
        #pragma unroll
        for (int j = 0; j < 8; j++) {
            CP16(dq + OQH + j*16, gQh + go + j*16);
            CP16(dq + OQL + j*16, gQl + go + j*16);
        }
    }

    // ---- split K / V gather issuers: 64 keys x 2 halves x 2 col-chunks ----
    auto issueK = [&](int kt, int buf) {
        int key = t >> 2, half = (t >> 1) & 1, c = t & 1;
        int k = kt*64 + key;
        int src = half ? si1[k] : si0[k];
        size_t go = (rowbase + src) * 128 + c*64;
        uint32_t base = sb + OKV + buf*KVBUF + (uint32_t)key*QSTR + half*128 + c*64;
        #pragma unroll
        for (int j = 0; j < 4; j++) {
            CP16(base + OFF_KH + j*16, gKh + go + j*16);
            CP16(base + OFF_KL + j*16, gKl + go + j*16);
        }
    };
    auto issueV = [&](int kt, int buf) {
        int key = t >> 2, half = (t >> 1) & 1, c = t & 1;
        int k = kt*64 + key;
        int src = half ? si1[k] : si0[k];
        size_t go = (rowbase + src) * 128 + c*64;
        uint32_t base = sb + OKV + buf*KVBUF + (uint32_t)key*QSTR + half*128 + c*64;
        #pragma unroll
        for (int j = 0; j < 4; j++) {
            CP16(base + OFF_VH + j*16, gVh + go + j*16);
            CP16(base + OFF_VL + j*16, gVl + go + j*16);
        }
    };

    issueK(0, 0);
    issueV(0, 0);
    CP_COMMIT();                       // G0 (includes Q gathers)

    // per-lane ldmatrix offsets
    int l15 = lane & 15;
    uint32_t aH = sb + OQH + (w*16 + l15)*QSTR + (lane >> 4)*16;
    uint32_t aL = sb + OQL + (w*16 + l15)*QSTR + (lane >> 4)*16;
    uint32_t bOff4 = (lane & 7)*QSTR + ((lane >> 3) & 3)*16;   // K x4
    uint32_t vOff4 = (uint32_t)l15*QSTR + (lane >> 4)*16;      // V x4t

    float st[32], ot[64];
    #pragma unroll
    for (int i = 0; i < 64; i++) ot[i] = 0.f;
    float mref0 = 0.f, mref1 = 0.f, lr0 = 0.f, lr1 = 0.f;
    uint32_t pph0[8], pph1[8], ppl0[8], ppl1[8];   // P(t-1), persistent

    auto do_qk = [&](int buf) {
        uint32_t kbH = sb + OKV + buf*KVBUF + OFF_KH + bOff4;
        uint32_t kbL = sb + OKV + buf*KVBUF + OFF_KL + bOff4;
        #pragma unroll
        for (int i = 0; i < 32; i++) st[i] = 0.f;
        #pragma unroll
        for (int ksp = 0; ksp < 4; ksp++) {
            uint32_t ah0[4], al0[4], ah1[4], al1[4];
            ldsm_x4(ah0, aH + (2*ksp)*32);
            ldsm_x4(al0, aL + (2*ksp)*32);
            ldsm_x4(ah1, aH + (2*ksp+1)*32);
            ldsm_x4(al1, aL + (2*ksp+1)*32);
            #pragma unroll
            for (int nt = 0; nt < 8; nt++) {
                uint32_t bh[4], bl[4];
                ldsm_x4(bh, kbH + nt*8*QSTR + ksp*64);
                ldsm_x4(bl, kbL + nt*8*QSTR + ksp*64);
                mma16816(st + nt*4, ah0, bh);
                mma16816(st + nt*4, ah0, bl);
                mma16816(st + nt*4, al0, bh);
                mma16816(st + nt*4, ah1, bh + 2);
                mma16816(st + nt*4, ah1, bl + 2);
                mma16816(st + nt*4, al1, bh + 2);
            }
        }
    };

    auto do_pv = [&](int buf) {
        uint32_t vbH = sb + OKV + buf*KVBUF + OFF_VH + vOff4;
        uint32_t vbL = sb + OKV + buf*KVBUF + OFF_VL + vOff4;
        #pragma unroll
        for (int tt = 0; tt < 4; tt++) {
            uint32_t aPh[4] = { pph0[2*tt], pph1[2*tt], pph0[2*tt+1], pph1[2*tt+1] };
            uint32_t aPl[4] = { ppl0[2*tt], ppl1[2*tt], ppl0[2*tt+1], ppl1[2*tt+1] };
            #pragma unroll
            for (int ntp = 0; ntp < 8; ntp++) {
                uint32_t vh[4], vl[4];
                ldsm_x4t(vh, vbH + tt*16*QSTR + ntp*32);
                ldsm_x4t(vl, vbL + tt*16*QSTR + ntp*32);
                mma16816(ot + (2*ntp)*4,   aPh, vh);
                mma16816(ot + (2*ntp)*4,   aPh, vl);
                mma16816(ot + (2*ntp)*4,   aPl, vh);
                mma16816(ot + (2*ntp+1)*4, aPh, vh + 2);
                mma16816(ot + (2*ntp+1)*4, aPh, vl + 2);
                mma16816(ot + (2*ntp+1)*4, aPl, vh + 2);
            }
        }
    };

    auto do_softmax = [&](int kt) {
        if (kt == 0) {
            float m0 = -CUDART_INF_F, m1 = -CUDART_INF_F;
            #pragma unroll
            for (int nt = 0; nt < 8; nt++) {
                m0 = fmaxf(m0, fmaxf(st[nt*4],   st[nt*4+1]));
                m1 = fmaxf(m1, fmaxf(st[nt*4+2], st[nt*4+3]));
            }
            m0 = fmaxf(m0, __shfl_xor_sync(0xffffffffu, m0, 1));
            m0 = fmaxf(m0, __shfl_xor_sync(0xffffffffu, m0, 2));
            m1 = fmaxf(m1, __shfl_xor_sync(0xffffffffu, m1, 1));
            m1 = fmaxf(m1, __shfl_xor_sync(0xffffffffu, m1, 2));
            mref0 = m0; mref1 = m1;
        }
        #pragma unroll
        for (int nt = 0; nt < 8; nt++) {
            float p00 = __expf(st[nt*4]   - mref0);
            float p01 = __expf(st[nt*4+1] - mref0);
            float p10 = __expf(st[nt*4+2] - mref1);
            float p11 = __expf(st[nt*4+3] - mref1);
            lr0 += p00 + p01;
            lr1 += p10 + p11;
            split2(p00, p01, pph0[nt], ppl0[nt]);
            split2(p10, p11, pph1[nt], ppl1[nt]);
        }
    };

    // ---- iter 0 ----
    issueK(1, 1); CP_COMMIT();         // G1
    CP_WAIT(1); __syncthreads();       // G0 done: Q, K0, V0
    do_qk(0);
    do_softmax(0);                     // -> P(0)
    __syncthreads();
    issueV(1, 1); CP_COMMIT();         // G2

    // ---- iters 1..15: QK(t) -> PV(t-1) -> softmax(t) ----
    for (int kt = 1; kt < 16; kt++) {
        int buf = kt & 1;
        if (kt < 15) { issueK(kt+1, buf ^ 1); CP_COMMIT(); }
        if (kt < 15) { CP_WAIT(2); } else { CP_WAIT(1); }
        __syncthreads();               // K(t), V(t-1) visible
        do_qk(buf);
        do_pv(buf ^ 1);                // PV(t-1): tensor stays hot
        do_softmax(kt);                // -> P(t)
        __syncthreads();               // PV(t-1) done reading vbuf[buf^1]
        if (kt < 15) { issueV(kt+1, buf ^ 1); CP_COMMIT(); }
    }

    // ---- tail: PV(15) ----
    CP_WAIT(0); __syncthreads();
    do_pv(1);

    // ---- epilogue ----
    lr0 += __shfl_xor_sync(0xffffffffu, lr0, 1);
    lr0 += __shfl_xor_sync(0xffffffffu, lr0, 2);
    lr1 += __shfl_xor_sync(0xffffffffu, lr1, 1);
    lr1 += __shfl_xor_sync(0xffffffffu, lr1, 2);
    float inv0 = 0.08838834764831845f / lr0;   // 1/sqrt(2D)
    float inv1 = 0.08838834764831845f / lr1;

    int r0 = tile*128 + w*16 + (lane >> 2);
    int colb = (lane & 3) * 2;
    if (r0 < cnt) {
        int q = listp[r0];
        float* op = out + ((size_t)(b*SEQ + q))*512 + (h & 3)*128;
        #pragma unroll
        for (int nt = 0; nt < 16; nt++)
            *(float2*)(op + nt*8 + colb) = make_float2(ot[nt*4]*inv0, ot[nt*4+1]*inv0);
    }
    int r1 = r0 + 8;
    if (r1 < cnt) {
        int q = listp[r1];
        float* op = out + ((size_t)(b*SEQ + q))*512 + (h & 3)*128;
        #pragma unroll
        for (int nt = 0; nt < 16; nt++)
            *(float2*)(op + nt*8 + colb) = make_float2(ot[nt*4+2]*inv1, ot[nt*4+3]*inv1);
    }
}

// ---------------- launch ----------------
extern "C" void kernel_launch(void* const* d_in, const int* in_sizes, int n_in,
                              void* d_out, int out_size) {
    const float* Q = (const float*)d_in[0];
    const float* K = (const float*)d_in[1];
    const float* V = (const float*)d_in[2];
    const float* C = (const float*)d_in[3];
    float* out = (float*)d_out;

    cudaFuncSetAttribute(attn_kernel, cudaFuncAttributeMaxDynamicSharedMemorySize, ASMEM);

    init_kernel<<<1, 32>>>();
    pairs_kernel<<<BATCH*SEQ, 256>>>(C);
    convert_kernel<<<dim3(NELEM/1024, 3), 256>>>(Q, K, V);
    attn_kernel<<<dim3(8, HEADS, BATCH), 256, ASMEM>>>(out);
}

// round 16
// speedup vs baseline: 1.2741x; 1.1438x over previous
#include <cuda_runtime.h>
#include <cuda_fp16.h>
#include <cstdint>
#include <math_constants.h>

#define BATCH 16
#define HEADS 8
#define SEQ   1024
#define DIM   64

// ---------------- scratch ----------------
__device__ int g_i0[BATCH*SEQ];
__device__ int g_i1[BATCH*SEQ];
__device__ int g_list[BATCH*2*SEQ];
__device__ int g_cnt[BATCH*2];

// Flat fp16 hi/lo arrays, same [b,h,s,d] layout as inputs. 16 MB each.
#define NELEM (BATCH*HEADS*SEQ*DIM)
__device__ __align__(16) unsigned char gQh[NELEM*2];
__device__ __align__(16) unsigned char gQl[NELEM*2];
__device__ __align__(16) unsigned char gKh[NELEM*2];
__device__ __align__(16) unsigned char gKl[NELEM*2];
__device__ __align__(16) unsigned char gVh[NELEM*2];
__device__ __align__(16) unsigned char gVl[NELEM*2];

// ---------------- asm helpers (sm_80-level PTX only) ----------------
__device__ __forceinline__ uint32_t smem_u32(const void* p) {
    uint32_t a;
    asm("{ .reg .u64 t; cvta.to.shared.u64 t, %1; cvt.u32.u64 %0, t; }" : "=r"(a) : "l"(p));
    return a;
}
__device__ __forceinline__ void ldsm_x4(uint32_t* r, uint32_t addr) {
    asm volatile("ldmatrix.sync.aligned.m8n8.x4.shared.b16 {%0,%1,%2,%3}, [%4];"
        : "=r"(r[0]), "=r"(r[1]), "=r"(r[2]), "=r"(r[3]) : "r"(addr));
}
__device__ __forceinline__ void ldsm_x4t(uint32_t* r, uint32_t addr) {
    asm volatile("ldmatrix.sync.aligned.m8n8.x4.trans.shared.b16 {%0,%1,%2,%3}, [%4];"
        : "=r"(r[0]), "=r"(r[1]), "=r"(r[2]), "=r"(r[3]) : "r"(addr));
}
__device__ __forceinline__ void mma16816(float* d, const uint32_t* a, const uint32_t* b) {
    asm volatile("mma.sync.aligned.m16n8k16.row.col.f32.f16.f16.f32 "
        "{%0,%1,%2,%3}, {%4,%5,%6,%7}, {%8,%9}, {%0,%1,%2,%3};"
        : "+f"(d[0]), "+f"(d[1]), "+f"(d[2]), "+f"(d[3])
        : "r"(a[0]), "r"(a[1]), "r"(a[2]), "r"(a[3]), "r"(b[0]), "r"(b[1]));
}
#define CP16(dst, src) asm volatile("cp.async.cg.shared.global [%0], [%1], 16;" :: "r"(dst), "l"(src))
#define CP_COMMIT()    asm volatile("cp.async.commit_group;" ::: "memory")
#define CP_WAIT(n)     asm volatile("cp.async.wait_group %0;" :: "n"(n) : "memory")

__device__ __forceinline__ void split2h(float a, float b, uint32_t& h, uint32_t& l) {
    __half2 hv = __floats2half2_rn(a, b);
    float2 hf = __half22float2(hv);
    __half2 lv = __floats2half2_rn(a - hf.x, b - hf.y);
    h = *reinterpret_cast<uint32_t*>(&hv);
    l = *reinterpret_cast<uint32_t*>(&lv);
}
__device__ __forceinline__ uint32_t pack2h(float a, float b) {
    __half2 hv = __floats2half2_rn(a, b);
    return *reinterpret_cast<uint32_t*>(&hv);
}

// ---------------- init + pairs (exact, unchanged) ----------------
__global__ void init_kernel() {
    int t = threadIdx.x;
    if (t < BATCH*2) g_cnt[t] = 0;
}

__global__ __launch_bounds__(256) void pairs_kernel(const float* __restrict__ centers) {
    int bs = blockIdx.x;
    int b = bs >> 10, s = bs & 1023;
    const float4* cp = (const float4*)centers;
    float4 bb = cp[bs];
    float x1 = bb.x - 0.5f*bb.w, y1 = bb.y - 0.5f*bb.z;
    float x2 = bb.x + 0.5f*bb.w, y2 = bb.y + 0.5f*bb.z;
    float areas = __fmul_rn(__fsub_rn(x2,x1), __fsub_rn(y2,y1));
    float best = -CUDART_INF_F; int bidx = 0;
    for (int k = threadIdx.x; k < SEQ; k += 256) {
        float4 cb = cp[(b<<10)+k];
        float kx1 = cb.x - 0.5f*cb.w, ky1 = cb.y - 0.5f*cb.z;
        float kx2 = cb.x + 0.5f*cb.w, ky2 = cb.y + 0.5f*cb.z;
        float iw = __fsub_rn(fminf(x2,kx2), fmaxf(x1,kx1));
        float ih = __fsub_rn(fminf(y2,ky2), fmaxf(y1,ky1));
        float inter = __fmul_rn(iw, ih);
        float ka = __fmul_rn(__fsub_rn(kx2,kx1), __fsub_rn(ky2,ky1));
        float uni = __fsub_rn(__fadd_rn(areas, ka), inter);
        float iou = __fdiv_rn(inter, uni);
        if (k == s) iou = __fsub_rn(iou, 1.0f);
        if (iou > best) { best = iou; bidx = k; }
    }
    __shared__ float sv[256]; __shared__ int si[256];
    int t = threadIdx.x;
    sv[t] = best; si[t] = bidx;
    __syncthreads();
    for (int off = 128; off > 0; off >>= 1) {
        if (t < off) {
            float v2 = sv[t+off]; int i2 = si[t+off];
            if (v2 > sv[t] || (v2 == sv[t] && i2 < si[t])) { sv[t] = v2; si[t] = i2; }
        }
        __syncthreads();
    }
    if (t == 0) {
        int p = si[0];
        float l1s = __fadd_rn(fabsf(__fsub_rn(x2,x1)), fabsf(__fsub_rn(y2,y1)));
        float4 pb = cp[(b<<10)+p];
        float px1 = pb.x - 0.5f*pb.w, py1 = pb.y - 0.5f*pb.z;
        float px2 = pb.x + 0.5f*pb.w, py2 = pb.y + 0.5f*pb.z;
        float l1p = __fadd_rn(fabsf(__fsub_rn(px2,px1)), fabsf(__fsub_rn(py2,py1)));
        bool keep0 = (l1s >= l1p);
        g_i0[bs] = keep0 ? s : p;
        g_i1[bs] = keep0 ? p : s;
        int g = keep0 ? 0 : 1;
        int slot = atomicAdd(&g_cnt[b*2 + g], 1);
        g_list[(b*2 + g)*SEQ + slot] = s;
    }
}

// ---------------- streaming fp32 -> fp16 hi/lo convert ----------------
__global__ __launch_bounds__(256) void convert_kernel(
    const float* __restrict__ Q, const float* __restrict__ K, const float* __restrict__ V)
{
    int tid = blockIdx.x*256 + threadIdx.x;              // float4 index
    int which = blockIdx.y;
    const float4* s = (const float4*)(which == 0 ? Q : (which == 1 ? K : V));
    uint2* dh = (uint2*)(which == 0 ? gQh : (which == 1 ? gKh : gVh));
    uint2* dl = (uint2*)(which == 0 ? gQl : (which == 1 ? gKl : gVl));
    float4 v = s[tid];
    uint2 uh, ul;
    split2h(v.x, v.y, uh.x, ul.x);
    split2h(v.z, v.w, uh.y, ul.y);
    dh[tid] = uh;
    dl[tid] = ul;
}

// ---------------- HMMA flash attention (fp16, online-max softmax) ----------------
// smem: Qh 128x272=34816, Ql 34816, 2 KV bufs {Kh,Kl,Vh,Vl} 64x272=17408 each
// -> 69632/buf; idx 8192. Total 217088 (1 CTA/SM).
#define QSTR   272
#define OQH    0
#define OQL    34816
#define OKV    69632
#define KVBUF  69632
#define OFF_KH 0
#define OFF_KL 17408
#define OFF_VH 34816
#define OFF_VL 52224
#define OIDX0  208896
#define OIDX1  (208896 + 4096)
#define ASMEM  (208896 + 8192)

__global__ __launch_bounds__(256, 1) void attn_kernel(float* __restrict__ out) {
    int tile = blockIdx.x, h = blockIdx.y, b = blockIdx.z;
    int g = h >> 2;
    int cnt = g_cnt[b*2 + g];
    if (tile*128 >= cnt) return;

    extern __shared__ char sm[];
    uint32_t sb = smem_u32(sm);
    int t = threadIdx.x, lane = t & 31, w = t >> 5;
    int* si0 = (int*)(sm + OIDX0);
    int* si1 = (int*)(sm + OIDX1);

    // stage pair indices for this batch into smem
    {
        const int* p0 = g_i0 + b*SEQ;
        const int* p1 = g_i1 + b*SEQ;
        #pragma unroll
        for (int i = 0; i < 4; i++) {
            si0[t + i*256] = p0[t + i*256];
            si1[t + i*256] = p1[t + i*256];
        }
    }
    __syncthreads();

    const size_t rowbase = (size_t)(b*HEADS + h) * SEQ;   // 128 B source rows
    const int* listp = g_list + (b*2+g)*SEQ;

    // ---- Q tile gather: thread = one (row, half); 8+8 cp16 ----
    {
        int row = t >> 1, half = t & 1;
        int idx = tile*128 + row; if (idx >= cnt) idx = cnt - 1;
        int q = listp[idx];
        int src = half ? si1[q] : si0[q];
        size_t go = (rowbase + src) * 128;
        uint32_t dq = sb + (half ? 128u : 0u) + (uint32_t)row*QSTR;
        #pragma unroll
        for (int j = 0; j < 8; j++) {
            CP16(dq + OQH + j*16, gQh + go + j*16);
            CP16(dq + OQL + j*16, gQl + go + j*16);
        }
    }

    // ---- K/V tile gather issuer: 64 keys x 2 halves x 2 col-chunks ----
    auto issue = [&](int kt, int buf) {
        int key = t >> 2, half = (t >> 1) & 1, c = t & 1;
        int k = kt*64 + key;
        int src = half ? si1[k] : si0[k];
        size_t go = (rowbase + src) * 128 + c*64;
        uint32_t base = sb + OKV + buf*KVBUF + (uint32_t)key*QSTR + half*128 + c*64;
        #pragma unroll
        for (int j = 0; j < 4; j++) {
            CP16(base + OFF_KH + j*16, gKh + go + j*16);
            CP16(base + OFF_KL + j*16, gKl + go + j*16);
            CP16(base + OFF_VH + j*16, gVh + go + j*16);
            CP16(base + OFF_VL + j*16, gVl + go + j*16);
        }
    };

    issue(0, 0);
    CP_COMMIT();

    // per-lane ldmatrix offsets
    int l15 = lane & 15;
    uint32_t aH = sb + OQH + (w*16 + l15)*QSTR + (lane >> 4)*16;
    uint32_t aL = sb + OQL + (w*16 + l15)*QSTR + (lane >> 4)*16;
    uint32_t bOff4 = (lane & 7)*QSTR + ((lane >> 3) & 3)*16;   // K x4
    uint32_t vOff4 = (uint32_t)l15*QSTR + (lane >> 4)*16;      // V x4t

    float st[32], ot[64];
    #pragma unroll
    for (int i = 0; i < 64; i++) ot[i] = 0.f;
    float mrun0 = -CUDART_INF_F, mrun1 = -CUDART_INF_F, lr0 = 0.f, lr1 = 0.f;
    int buf = 0;

    for (int kt = 0; kt < 16; kt++) {
        if (kt < 15) { issue(kt+1, buf ^ 1); CP_COMMIT(); CP_WAIT(1); }
        else         { CP_WAIT(0); }
        __syncthreads();

        uint32_t kbH = sb + OKV + buf*KVBUF + OFF_KH + bOff4;
        uint32_t kbL = sb + OKV + buf*KVBUF + OFF_KL + bOff4;
        uint32_t vbH = sb + OKV + buf*KVBUF + OFF_VH + vOff4;
        uint32_t vbL = sb + OKV + buf*KVBUF + OFF_VL + vOff4;

        // ---- QK: S = QhKh + QhKl + QlKh  (fp16 splits; k-step pairs) ----
        #pragma unroll
        for (int i = 0; i < 32; i++) st[i] = 0.f;
        #pragma unroll
        for (int ksp = 0; ksp < 4; ksp++) {
            uint32_t ah0[4], al0[4], ah1[4], al1[4];
            ldsm_x4(ah0, aH + (2*ksp)*32);
            ldsm_x4(al0, aL + (2*ksp)*32);
            ldsm_x4(ah1, aH + (2*ksp+1)*32);
            ldsm_x4(al1, aL + (2*ksp+1)*32);
            #pragma unroll
            for (int nt = 0; nt < 8; nt++) {
                uint32_t bh[4], bl[4];
                ldsm_x4(bh, kbH + nt*8*QSTR + ksp*64);
                ldsm_x4(bl, kbL + nt*8*QSTR + ksp*64);
                mma16816(st + nt*4, ah0, bh);
                mma16816(st + nt*4, ah0, bl);
                mma16816(st + nt*4, al0, bh);
                mma16816(st + nt*4, ah1, bh + 2);
                mma16816(st + nt*4, ah1, bl + 2);
                mma16816(st + nt*4, al1, bh + 2);
            }
        }

        // ---- online softmax: running max keeps P <= 1 (fp16-safe) ----
        float m0 = -CUDART_INF_F, m1 = -CUDART_INF_F;
        #pragma unroll
        for (int nt = 0; nt < 8; nt++) {
            m0 = fmaxf(m0, fmaxf(st[nt*4],   st[nt*4+1]));
            m1 = fmaxf(m1, fmaxf(st[nt*4+2], st[nt*4+3]));
        }
        m0 = fmaxf(m0, __shfl_xor_sync(0xffffffffu, m0, 1));
        m0 = fmaxf(m0, __shfl_xor_sync(0xffffffffu, m0, 2));
        m1 = fmaxf(m1, __shfl_xor_sync(0xffffffffu, m1, 1));
        m1 = fmaxf(m1, __shfl_xor_sync(0xffffffffu, m1, 2));
        float mn0 = fmaxf(mrun0, m0), mn1 = fmaxf(mrun1, m1);
        float corr0 = __expf(mrun0 - mn0);   // 0 on first tile (-inf)
        float corr1 = __expf(mrun1 - mn1);
        mrun0 = mn0; mrun1 = mn1;
        #pragma unroll
        for (int i = 0; i < 16; i++) {
            ot[4*i]   *= corr0; ot[4*i+1] *= corr0;
            ot[4*i+2] *= corr1; ot[4*i+3] *= corr1;
        }
        uint32_t pph0[8], pph1[8];
        float ls0 = 0.f, ls1 = 0.f;
        #pragma unroll
        for (int nt = 0; nt < 8; nt++) {
            float p00 = __expf(st[nt*4]   - mn0);
            float p01 = __expf(st[nt*4+1] - mn0);
            float p10 = __expf(st[nt*4+2] - mn1);
            float p11 = __expf(st[nt*4+3] - mn1);
            ls0 += p00 + p01;
            ls1 += p10 + p11;
            pph0[nt] = pack2h(p00, p01);
            pph1[nt] = pack2h(p10, p11);
        }
        lr0 = lr0*corr0 + ls0;
        lr1 = lr1*corr1 + ls1;

        // ---- PV: O += P*Vh + P*Vl  (2 passes; d-block pairs) ----
        #pragma unroll
        for (int tt = 0; tt < 4; tt++) {
            uint32_t aP[4] = { pph0[2*tt], pph1[2*tt], pph0[2*tt+1], pph1[2*tt+1] };
            #pragma unroll
            for (int ntp = 0; ntp < 8; ntp++) {
                uint32_t vh[4], vl[4];
                ldsm_x4t(vh, vbH + tt*16*QSTR + ntp*32);
                ldsm_x4t(vl, vbL + tt*16*QSTR + ntp*32);
                mma16816(ot + (2*ntp)*4,   aP, vh);
                mma16816(ot + (2*ntp)*4,   aP, vl);
                mma16816(ot + (2*ntp+1)*4, aP, vh + 2);
                mma16816(ot + (2*ntp+1)*4, aP, vl + 2);
            }
        }
        __syncthreads();
        buf ^= 1;
    }

    // ---- epilogue ----
    lr0 += __shfl_xor_sync(0xffffffffu, lr0, 1);
    lr0 += __shfl_xor_sync(0xffffffffu, lr0, 2);
    lr1 += __shfl_xor_sync(0xffffffffu, lr1, 1);
    lr1 += __shfl_xor_sync(0xffffffffu, lr1, 2);
    float inv0 = 0.08838834764831845f / lr0;   // 1/sqrt(2D)
    float inv1 = 0.08838834764831845f / lr1;

    int r0 = tile*128 + w*16 + (lane >> 2);
    int colb = (lane & 3) * 2;
    if (r0 < cnt) {
        int q = listp[r0];
        float* op = out + ((size_t)(b*SEQ + q))*512 + (h & 3)*128;
        #pragma unroll
        for (int nt = 0; nt < 16; nt++)
            *(float2*)(op + nt*8 + colb) = make_float2(ot[nt*4]*inv0, ot[nt*4+1]*inv0);
    }
    int r1 = r0 + 8;
    if (r1 < cnt) {
        int q = listp[r1];
        float* op = out + ((size_t)(b*SEQ + q))*512 + (h & 3)*128;
        #pragma unroll
        for (int nt = 0; nt < 16; nt++)
            *(float2*)(op + nt*8 + colb) = make_float2(ot[nt*4+2]*inv1, ot[nt*4+3]*inv1);
    }
}

// ---------------- launch ----------------
extern "C" void kernel_launch(void* const* d_in, const int* in_sizes, int n_in,
                              void* d_out, int out_size) {
    const float* Q = (const float*)d_in[0];
    const float* K = (const float*)d_in[1];
    const float* V = (const float*)d_in[2];
    const float* C = (const float*)d_in[3];
    float* out = (float*)d_out;

    cudaFuncSetAttribute(attn_kernel, cudaFuncAttributeMaxDynamicSharedMemorySize, ASMEM);

    init_kernel<<<1, 32>>>();
    pairs_kernel<<<BATCH*SEQ, 256>>>(C);
    convert_kernel<<<dim3(NELEM/1024, 3), 256>>>(Q, K, V);
    attn_kernel<<<dim3(8, HEADS, BATCH), 256, ASMEM>>>(out);
}